// round 10
// baseline (speedup 1.0000x reference)
#include <cuda_runtime.h>

namespace {
constexpr int B=2, N=512, M=512, DQ=128, DK=128, DE=64, DKE=192, H=8, O=32, OUTD=128;
}

__device__ __align__(16) float g_qk  [(size_t)B*N*DKE*H];   // [b][n][i][h]
__device__ __align__(16) float g_keyT[(size_t)B*DK*M];      // [b][i][m]
__device__ __align__(16) float g_v   [(size_t)B*M*H*O];     // [b][m][h][o]
__device__ __align__(16) float g_attn[(size_t)B*H*N*M];
__device__ __align__(16) float g_mh  [(size_t)B*N*H*O];

typedef unsigned long long u64;
__device__ __forceinline__ u64 pack2(float lo, float hi) {
    u64 r; asm("mov.b64 %0, {%1,%2};" : "=l"(r) : "f"(lo), "f"(hi)); return r;
}
__device__ __forceinline__ void fma2(u64& d, u64 a, u64 b) {
    asm("fma.rn.f32x2 %0, %1, %2, %0;" : "+l"(d) : "l"(a), "l"(b));
}
__device__ __forceinline__ float2 unpack2(u64 v) {
    float2 r; asm("mov.b64 {%0,%1}, %2;" : "=f"(r.x), "=f"(r.y) : "l"(v)); return r;
}

// ---------------------------------------------------------------------------
// K_pre: fused keyT (blocks 0..127) | qk (128..255) | v (256..383)
// ---------------------------------------------------------------------------
__global__ __launch_bounds__(256) void k_pre(const float* __restrict__ key,
                                             const float* __restrict__ query,
                                             const float* __restrict__ Wq,
                                             const float* __restrict__ Wk,
                                             const float* __restrict__ value,
                                             const float* __restrict__ Wv) {
    __shared__ float sm[3072];
    const int t = threadIdx.x;

    if (blockIdx.x < 128) {            // ---- keyT ----
        float (*ts)[33] = (float(*)[33])sm;
        const int x=blockIdx.x, b=x>>6, mt=(x&63)>>2, it=x&3;
        const int m0=mt<<5, i0=it<<5;
        #pragma unroll
        for (int j=0;j<4;j++){int idx=t+256*j,r=idx>>5,c=idx&31;
            ts[r][c]=key[((size_t)b*M+m0+r)*DK+i0+c];}
        __syncthreads();
        #pragma unroll
        for (int j=0;j<4;j++){int idx=t+256*j,r=idx>>5,c=idx&31;
            g_keyT[((size_t)b*DK+i0+r)*M+m0+c]=ts[c][r];}
    } else if (blockIdx.x < 256) {     // ---- qk ----
        float (*xs)[DQ]  = (float(*)[DQ])sm;
        float (*qs)[H*O] = (float(*)[H*O])(sm + 8*DQ);
        const int xb=blockIdx.x-128, b=xb>>6, n0=(xb&63)<<3;
        #pragma unroll
        for (int j=0;j<4;j++){int idx=t+256*j,nl=idx>>7,d=idx&127;
            xs[nl][d]=query[((size_t)(b*N+n0+nl))*DQ+d];}
        __syncthreads();
        {
            const int h=t>>5,o=t&31;
            float acc[8];
            #pragma unroll
            for (int nl=0;nl<8;nl++) acc[nl]=0.f;
            const float* wq=Wq+((size_t)h*DQ)*O+o;
            for (int d=0;d<DQ;d++){float w=wq[(size_t)d*O];
                #pragma unroll
                for (int nl=0;nl<8;nl++) acc[nl]=fmaf(xs[nl][d],w,acc[nl]);}
            const float scale=0.17677669529663688f; // 1/sqrt(32)
            #pragma unroll
            for (int nl=0;nl<8;nl++) qs[nl][t]=acc[nl]*scale;
        }
        __syncthreads();
        #pragma unroll
        for (int j=0;j<6;j++){
            int p=t+256*j,h=p/DKE,i=p-h*DKE;
            const float* wk=Wk+((size_t)h*DKE+i)*O;
            float acc[8];
            #pragma unroll
            for (int nl=0;nl<8;nl++) acc[nl]=0.f;
            for (int o=0;o<O;o++){float w=wk[o];
                #pragma unroll
                for (int nl=0;nl<8;nl++) acc[nl]=fmaf(qs[nl][h*O+o],w,acc[nl]);}
            #pragma unroll
            for (int nl=0;nl<8;nl++)
                g_qk[((size_t)(b*N+n0+nl)*DKE+i)*H+h]=acc[nl];
        }
    } else {                           // ---- v ----
        float (*xs)[DK] = (float(*)[DK])sm;
        const int xb=blockIdx.x-256, b=xb>>6, m0=(xb&63)<<3;
        #pragma unroll
        for (int j=0;j<4;j++){int idx=t+256*j,ml=idx>>7,d=idx&127;
            xs[ml][d]=value[((size_t)(b*M+m0+ml))*DK+d];}
        __syncthreads();
        const int h=t>>5,o=t&31;
        float acc[8];
        #pragma unroll
        for (int ml=0;ml<8;ml++) acc[ml]=0.f;
        const float* wv=Wv+((size_t)h*DK)*O+o;
        for (int d=0;d<DK;d++){float w=wv[(size_t)d*O];
            #pragma unroll
            for (int ml=0;ml<8;ml++) acc[ml]=fmaf(xs[ml][d],w,acc[ml]);}
        #pragma unroll
        for (int ml=0;ml<8;ml++)
            g_v[(((size_t)(b*M+m0+ml))*H+h)*O+o]=acc[ml];
    }
}

// ---------------------------------------------------------------------------
// K2 v5: block = 2 n, 256 threads, thread owns m-pair (2t, 2t+1).
// acc = 16 u64 (32 regs) -> 3 blocks/SM, 6 warps/SMSP for latency hiding.
// Per i: key X = coalesced LDG.64 (f32x2 operand); 8 broadcast LDS.128 feed
// 16 FFMA2. Edge staged in 8-i slices, pitch-516 (conflict-free).
// ---------------------------------------------------------------------------
__global__ __launch_bounds__(256,3) void k_attn(const float* __restrict__ edge) {
    __shared__ __align__(16) u64   qk2[2*DKE*H];   // 24.6 KB [n][i][h] pairs
    __shared__ __align__(16) float xs[8*516];      // 16.5 KB edge slice [i][m]
    __shared__ float redA[16*8], redB[16*8];

    const int x=blockIdx.x;            // B*N/2 = 512
    const int b=x>>8, n0=(x&255)<<1, t=threadIdx.x;
    const int w=t>>5, l=t&31;

    const float* gq=g_qk+(size_t)(b*N+n0)*(DKE*H);
    #pragma unroll
    for (int j=0;j<12;j++){float v=gq[t+256*j]; qk2[t+256*j]=pack2(v,v);}
    __syncthreads();

    u64 acc[2][8];
    #pragma unroll
    for (int n=0;n<2;n++)
        #pragma unroll
        for (int h=0;h<8;h++) acc[n][h]=0ull;

    // ---- key phase: X = keyT[b][i][2t..2t+1] ----
    {
        const u64* kT=(const u64*)(g_keyT+(size_t)b*DK*M);
        #pragma unroll 2
        for (int i=0;i<DK;i++){
            u64 X=kT[i*(M/2)+t];
            #pragma unroll
            for (int n=0;n<2;n++){
                const ulonglong2* A=(const ulonglong2*)(qk2+(n*DKE+i)*8);
                ulonglong2 a0=A[0],a1=A[1],a2=A[2],a3=A[3];
                fma2(acc[n][0],a0.x,X); fma2(acc[n][1],a0.y,X);
                fma2(acc[n][2],a1.x,X); fma2(acc[n][3],a1.y,X);
                fma2(acc[n][4],a2.x,X); fma2(acc[n][5],a2.y,X);
                fma2(acc[n][6],a3.x,X); fma2(acc[n][7],a3.y,X);
            }
        }
    }

    // ---- edge phase: per n, 8 slices of 8 i ----
    for (int n=0;n<2;n++){
        const float* eb=edge+((size_t)(b*N+n0+n)*M)*DE;
        for (int s=0;s<8;s++){
            __syncthreads();
            #pragma unroll
            for (int r=0;r<4;r++){
                int id=r*256+t, m=id>>1, c=id&1;
                float4 v=*(const float4*)(eb+(size_t)m*DE+s*8+4*c);
                float* p=xs+(4*c)*516+m;
                p[0]=v.x; p[516]=v.y; p[1032]=v.z; p[1548]=v.w;
            }
            __syncthreads();
            #pragma unroll
            for (int il=0;il<8;il++){
                u64 X=*(const u64*)(xs+il*516+2*t);
                const ulonglong2* A=(const ulonglong2*)(qk2+(s*8+il+DK)*8 + (size_t)n*DKE*8);
                ulonglong2 a0=A[0],a1=A[1],a2=A[2],a3=A[3];
                fma2(acc[n][0],a0.x,X); fma2(acc[n][1],a0.y,X);
                fma2(acc[n][2],a1.x,X); fma2(acc[n][3],a1.y,X);
                fma2(acc[n][4],a2.x,X); fma2(acc[n][5],a2.y,X);
                fma2(acc[n][6],a3.x,X); fma2(acc[n][7],a3.y,X);
            }
        }
    }
    __syncthreads();

    // ---- softmax over m (register logits; 8-warp reduce) ----
    #pragma unroll
    for (int n=0;n<2;n++)
        #pragma unroll
        for (int h=0;h<8;h++){
            float2 p=unpack2(acc[n][h]);
            float mx=fmaxf(p.x,p.y);
            #pragma unroll
            for (int s=16;s>0;s>>=1) mx=fmaxf(mx,__shfl_xor_sync(0xffffffffu,mx,s));
            if (l==0) redA[(n*8+h)*8+w]=mx;
        }
    __syncthreads();
    #pragma unroll
    for (int n=0;n<2;n++)
        #pragma unroll
        for (int h=0;h<8;h++){
            const int c=n*8+h;
            const float* ra=redA+c*8;
            float gm=fmaxf(fmaxf(fmaxf(ra[0],ra[1]),fmaxf(ra[2],ra[3])),
                           fmaxf(fmaxf(ra[4],ra[5]),fmaxf(ra[6],ra[7])));
            float2 p=unpack2(acc[n][h]);
            p.x=__expf(p.x-gm); p.y=__expf(p.y-gm);
            acc[n][h]=pack2(p.x,p.y);
            float sum=p.x+p.y;
            #pragma unroll
            for (int s=16;s>0;s>>=1) sum+=__shfl_xor_sync(0xffffffffu,sum,s);
            if (l==0) redB[c*8+w]=sum;
        }
    __syncthreads();
    #pragma unroll
    for (int n=0;n<2;n++)
        #pragma unroll
        for (int h=0;h<8;h++){
            const int c=n*8+h;
            const float* rb=redB+c*8;
            float inv=1.f/(((rb[0]+rb[1])+(rb[2]+rb[3]))+((rb[4]+rb[5])+(rb[6]+rb[7])));
            float2 p=unpack2(acc[n][h]);
            float2 o=make_float2(p.x*inv,p.y*inv);
            *(float2*)(g_attn+(((size_t)b*H+h)*N+n0+n)*M+2*t)=o;
        }
}

// ---------------------------------------------------------------------------
// K3: mh = attn @ v. 512 blocks (b,h,16-n), 128 threads.
// ---------------------------------------------------------------------------
__global__ __launch_bounds__(128) void k_av() {
    const int x=blockIdx.x;              // 2*8*32 = 512
    const int b=x>>8, h=(x>>5)&7, n0=(x&31)<<4;
    const int t=threadIdx.x, nl=t>>3, og=t&7;
    __shared__ __align__(16) float at[16][132];
    __shared__ __align__(16) float vt[128][32];
    u64 a01=0ull, a23=0ull;
    for (int mt=0;mt<4;mt++){
        const int mb=mt<<7;
        #pragma unroll
        for (int j=0;j<4;j++){int idx=t+128*j,r=idx>>5,c=idx&31;
            *(float4*)&at[r][c*4]=
                *(const float4*)(g_attn+(((size_t)b*H+h)*N+n0+r)*M+mb+c*4);}
        #pragma unroll
        for (int j=0;j<8;j++){int idx=t+128*j,ml=idx>>3,c=idx&7;
            *(float4*)&vt[ml][c*4]=
                *(const float4*)(g_v+(((size_t)b*M+mb+ml)*H+h)*O+c*4);}
        __syncthreads();
        #pragma unroll 8
        for (int m=0;m<128;m++){
            float a=at[nl][m];
            u64 a2=pack2(a,a);
            ulonglong2 V=*(const ulonglong2*)&vt[m][og*4];
            fma2(a01,a2,V.x);
            fma2(a23,a2,V.y);
        }
        __syncthreads();
    }
    float2 x01=unpack2(a01), x23=unpack2(a23);
    float4 outv=make_float4(x01.x,x01.y,x23.x,x23.y);
    *(float4*)&g_mh[((size_t)(b*N+n0+nl)*H+h)*O+og*4]=outv;
}

// ---------------------------------------------------------------------------
// K4 v3: out = mh @ Wp + bias. 256 blocks (4 n), 512 thr = (jj, k-quarter).
// 64-deep chains, 4 FMA chains/thread, smem combine of 4 partials.
// ---------------------------------------------------------------------------
__global__ __launch_bounds__(512) void k_proj(const float* __restrict__ Wp,
                                              const float* __restrict__ bias,
                                              float* __restrict__ out) {
    const int x=blockIdx.x;              // B*N/4 = 256
    const int b=x>>7, n0=(x&127)<<2, t=threadIdx.x;
    const int jj=t&127, kq=t>>7;         // k-quarter 0..3
    __shared__ float mhs[4][H*O];
    __shared__ float red[3][4][128];

    #pragma unroll
    for (int j=0;j<2;j++){
        int idx=t+512*j, nl=idx>>8, c=idx&255;
        mhs[nl][c]=g_mh[(size_t)(b*N+n0+nl)*(H*O)+c];
    }
    __syncthreads();

    float acc[4]={0.f,0.f,0.f,0.f};
    const float* wp=Wp+(size_t)(kq*64)*OUTD+jj;
    const int kb=kq*64;
    #pragma unroll 8
    for (int k=0;k<64;k++){
        float wv=wp[(size_t)k*OUTD];
        #pragma unroll
        for (int n=0;n<4;n++) acc[n]=fmaf(mhs[n][kb+k],wv,acc[n]);
    }
    if (kq>0){
        #pragma unroll
        for (int n=0;n<4;n++) red[kq-1][n][jj]=acc[n];
    }
    __syncthreads();
    if (kq==0){
        float bv=bias[jj];
        #pragma unroll
        for (int n=0;n<4;n++){
            float r=acc[n]+red[0][n][jj]+red[1][n][jj]+red[2][n][jj]+bv;
            out[(size_t)(b*N+n0+n)*OUTD+jj]=r;
        }
    }
}

extern "C" void kernel_launch(void* const* d_in, const int* in_sizes, int n_in,
                              void* d_out, int out_size) {
    (void)in_sizes; (void)n_in; (void)out_size;
    const float* query=(const float*)d_in[0];
    const float* key  =(const float*)d_in[1];
    const float* value=(const float*)d_in[2];
    const float* edge =(const float*)d_in[3];
    const float* Wq   =(const float*)d_in[4];
    const float* Wk   =(const float*)d_in[5];
    const float* Wv   =(const float*)d_in[6];
    const float* Wp   =(const float*)d_in[7];
    const float* bias =(const float*)d_in[8];
    float* out=(float*)d_out;

    k_pre <<<384,        256>>>(key,query,Wq,Wk,value,Wv);
    k_attn<<<B*(N/2),    256>>>(edge);
    k_av  <<<B*H*(N/16), 128>>>();
    k_proj<<<B*(N/4),    512>>>(Wp,bias,out);
}

// round 11
// speedup vs baseline: 1.1103x; 1.1103x over previous
#include <cuda_runtime.h>

namespace {
constexpr int B=2, N=512, M=512, DQ=128, DK=128, DE=64, DKE=192, H=8, O=32, OUTD=128;
}

__device__ __align__(16) float g_qk  [(size_t)B*N*DKE*H];   // [b][n][i][h]
__device__ __align__(16) float g_keyT[(size_t)B*DK*M];      // [b][i][m]
__device__ __align__(16) float g_v   [(size_t)B*M*H*O];     // [b][m][h][o]
__device__ __align__(16) float g_attn[(size_t)B*H*N*M];
__device__ __align__(16) float g_mh  [(size_t)B*N*H*O];

typedef unsigned long long u64;
__device__ __forceinline__ u64 pack2(float lo, float hi) {
    u64 r; asm("mov.b64 %0, {%1,%2};" : "=l"(r) : "f"(lo), "f"(hi)); return r;
}
__device__ __forceinline__ void fma2(u64& d, u64 a, u64 b) {
    asm("fma.rn.f32x2 %0, %1, %2, %0;" : "+l"(d) : "l"(a), "l"(b));
}
__device__ __forceinline__ float2 unpack2(u64 v) {
    float2 r; asm("mov.b64 {%0,%1}, %2;" : "=f"(r.x), "=f"(r.y) : "l"(v)); return r;
}

// ---------------------------------------------------------------------------
// K_pre: fused keyT (blocks 0..127) | qk (128..255) | v (256..383)
// ---------------------------------------------------------------------------
__global__ __launch_bounds__(256) void k_pre(const float* __restrict__ key,
                                             const float* __restrict__ query,
                                             const float* __restrict__ Wq,
                                             const float* __restrict__ Wk,
                                             const float* __restrict__ value,
                                             const float* __restrict__ Wv) {
    __shared__ float sm[3072];
    const int t = threadIdx.x;

    if (blockIdx.x < 128) {            // ---- keyT ----
        float (*ts)[33] = (float(*)[33])sm;
        const int x=blockIdx.x, b=x>>6, mt=(x&63)>>2, it=x&3;
        const int m0=mt<<5, i0=it<<5;
        #pragma unroll
        for (int j=0;j<4;j++){int idx=t+256*j,r=idx>>5,c=idx&31;
            ts[r][c]=key[((size_t)b*M+m0+r)*DK+i0+c];}
        __syncthreads();
        #pragma unroll
        for (int j=0;j<4;j++){int idx=t+256*j,r=idx>>5,c=idx&31;
            g_keyT[((size_t)b*DK+i0+r)*M+m0+c]=ts[c][r];}
    } else if (blockIdx.x < 256) {     // ---- qk ----
        float (*xs)[DQ]  = (float(*)[DQ])sm;
        float (*qs)[H*O] = (float(*)[H*O])(sm + 8*DQ);
        const int xb=blockIdx.x-128, b=xb>>6, n0=(xb&63)<<3;
        #pragma unroll
        for (int j=0;j<4;j++){int idx=t+256*j,nl=idx>>7,d=idx&127;
            xs[nl][d]=query[((size_t)(b*N+n0+nl))*DQ+d];}
        __syncthreads();
        {
            const int h=t>>5,o=t&31;
            float acc[8];
            #pragma unroll
            for (int nl=0;nl<8;nl++) acc[nl]=0.f;
            const float* wq=Wq+((size_t)h*DQ)*O+o;
            for (int d=0;d<DQ;d++){float w=wq[(size_t)d*O];
                #pragma unroll
                for (int nl=0;nl<8;nl++) acc[nl]=fmaf(xs[nl][d],w,acc[nl]);}
            const float scale=0.17677669529663688f; // 1/sqrt(32)
            #pragma unroll
            for (int nl=0;nl<8;nl++) qs[nl][t]=acc[nl]*scale;
        }
        __syncthreads();
        #pragma unroll
        for (int j=0;j<6;j++){
            int p=t+256*j,h=p/DKE,i=p-h*DKE;
            const float* wk=Wk+((size_t)h*DKE+i)*O;
            float acc[8];
            #pragma unroll
            for (int nl=0;nl<8;nl++) acc[nl]=0.f;
            for (int o=0;o<O;o++){float w=wk[o];
                #pragma unroll
                for (int nl=0;nl<8;nl++) acc[nl]=fmaf(qs[nl][h*O+o],w,acc[nl]);}
            #pragma unroll
            for (int nl=0;nl<8;nl++)
                g_qk[((size_t)(b*N+n0+nl)*DKE+i)*H+h]=acc[nl];
        }
    } else {                           // ---- v ----
        float (*xs)[DK] = (float(*)[DK])sm;
        const int xb=blockIdx.x-256, b=xb>>6, m0=(xb&63)<<3;
        #pragma unroll
        for (int j=0;j<4;j++){int idx=t+256*j,ml=idx>>7,d=idx&127;
            xs[ml][d]=value[((size_t)(b*M+m0+ml))*DK+d];}
        __syncthreads();
        const int h=t>>5,o=t&31;
        float acc[8];
        #pragma unroll
        for (int ml=0;ml<8;ml++) acc[ml]=0.f;
        const float* wv=Wv+((size_t)h*DK)*O+o;
        for (int d=0;d<DK;d++){float w=wv[(size_t)d*O];
            #pragma unroll
            for (int ml=0;ml<8;ml++) acc[ml]=fmaf(xs[ml][d],w,acc[ml]);}
        #pragma unroll
        for (int ml=0;ml<8;ml++)
            g_v[(((size_t)(b*M+m0+ml))*H+h)*O+o]=acc[ml];
    }
}

// prefetch one edge 8-i slice into registers (8 x LDG.128 per thread)
#define PF_LOAD(nn, ss) do {                                              \
    const float* ebp = edge + ((size_t)(bN + (nn))*M)*DE + (ss)*8;        \
    _Pragma("unroll")                                                     \
    for (int r=0;r<8;r++){ int id=r*128+t, m_=id>>1, c_=id&1;             \
        pf[r]=*(const float4*)(ebp + (size_t)m_*DE + 4*c_); }             \
} while(0)

// scatter the prefetch buffer into xs (conflict-free STS.32 pattern)
#define PF_STORE() do {                                                   \
    _Pragma("unroll")                                                     \
    for (int r=0;r<8;r++){ int id=r*128+t, m_=id>>1, c_=id&1;             \
        float* p=xs+(4*c_)*516+m_;                                        \
        p[0]=pf[r].x; p[516]=pf[r].y; p[1032]=pf[r].z; p[1548]=pf[r].w; } \
} while(0)

// 16 fma2 of one i against acc[n]
#define EDGE_FMA(nidx, iabs) do {                                         \
    ulonglong2 X=*(const ulonglong2*)(xs+il*516+4*t);                     \
    const ulonglong2* A=(const ulonglong2*)(qk2+((nidx)*DKE+(iabs))*8);   \
    ulonglong2 a0=A[0],a1=A[1],a2=A[2],a3=A[3];                           \
    fma2(acc[nidx][0][0],a0.x,X.x); fma2(acc[nidx][0][1],a0.x,X.y);       \
    fma2(acc[nidx][1][0],a0.y,X.x); fma2(acc[nidx][1][1],a0.y,X.y);       \
    fma2(acc[nidx][2][0],a1.x,X.x); fma2(acc[nidx][2][1],a1.x,X.y);       \
    fma2(acc[nidx][3][0],a1.y,X.x); fma2(acc[nidx][3][1],a1.y,X.y);       \
    fma2(acc[nidx][4][0],a2.x,X.x); fma2(acc[nidx][4][1],a2.x,X.y);       \
    fma2(acc[nidx][5][0],a2.y,X.x); fma2(acc[nidx][5][1],a2.y,X.y);       \
    fma2(acc[nidx][6][0],a3.x,X.x); fma2(acc[nidx][6][1],a3.x,X.y);       \
    fma2(acc[nidx][7][0],a3.y,X.x); fma2(acc[nidx][7][1],a3.y,X.y);       \
} while(0)

// ---------------------------------------------------------------------------
// K2 v6: v4 tile (2 n, 128 thr, m-quad) + register-prefetch edge pipeline.
// ---------------------------------------------------------------------------
__global__ __launch_bounds__(128,4) void k_attn(const float* __restrict__ edge) {
    __shared__ __align__(16) u64   qk2[2*DKE*H];   // 24.6 KB [n][i][h] pairs
    __shared__ __align__(16) float xs[8*516];      // 16.5 KB edge slice [i][m]
    __shared__ float redA[16*4], redB[16*4];

    const int x=blockIdx.x;            // B*N/2 = 512
    const int b=x>>8, n0=(x&255)<<1, t=threadIdx.x;
    const int w=t>>5, l=t&31;
    const int bN = b*N + n0;

    const float* gq=g_qk+(size_t)bN*(DKE*H);
    #pragma unroll
    for (int j=0;j<24;j++){float v=gq[t+128*j]; qk2[t+128*j]=pack2(v,v);}
    __syncthreads();

    u64 acc[2][8][2];
    #pragma unroll
    for (int n=0;n<2;n++)
        #pragma unroll
        for (int h=0;h<8;h++){acc[n][h][0]=0ull;acc[n][h][1]=0ull;}

    float4 pf[8];
    PF_LOAD(0,0);   // slice (n=0,s=0) loads overlap the whole key phase

    // ---- key phase: X = keyT[b][i][4t..4t+3] ----
    {
        const ulonglong2* kT=(const ulonglong2*)(g_keyT+(size_t)b*DK*M);
        #pragma unroll 2
        for (int i=0;i<DK;i++){
            ulonglong2 X=kT[i*(M/4)+t];
            #pragma unroll
            for (int n=0;n<2;n++){
                const ulonglong2* A=(const ulonglong2*)(qk2+(n*DKE+i)*8);
                ulonglong2 a0=A[0],a1=A[1],a2=A[2],a3=A[3];
                fma2(acc[n][0][0],a0.x,X.x); fma2(acc[n][0][1],a0.x,X.y);
                fma2(acc[n][1][0],a0.y,X.x); fma2(acc[n][1][1],a0.y,X.y);
                fma2(acc[n][2][0],a1.x,X.x); fma2(acc[n][2][1],a1.x,X.y);
                fma2(acc[n][3][0],a1.y,X.x); fma2(acc[n][3][1],a1.y,X.y);
                fma2(acc[n][4][0],a2.x,X.x); fma2(acc[n][4][1],a2.x,X.y);
                fma2(acc[n][5][0],a2.y,X.x); fma2(acc[n][5][1],a2.y,X.y);
                fma2(acc[n][6][0],a3.x,X.x); fma2(acc[n][6][1],a3.x,X.y);
                fma2(acc[n][7][0],a3.y,X.x); fma2(acc[n][7][1],a3.y,X.y);
            }
        }
    }

    // ---- edge phase: pipelined slices (n compile-time, s runtime) ----
    for (int s=0;s<8;s++){                    // n = 0
        __syncthreads();
        PF_STORE();
        if (s<7) PF_LOAD(0,s+1); else PF_LOAD(1,0);
        __syncthreads();
        #pragma unroll
        for (int il=0;il<8;il++){ EDGE_FMA(0, DK+s*8+il); }
    }
    for (int s=0;s<8;s++){                    // n = 1
        __syncthreads();
        PF_STORE();
        if (s<7) PF_LOAD(1,s+1);
        __syncthreads();
        #pragma unroll
        for (int il=0;il<8;il++){ EDGE_FMA(1, DK+s*8+il); }
    }
    __syncthreads();

    // ---- softmax over m (register logits, block reduce) ----
    #pragma unroll
    for (int n=0;n<2;n++)
        #pragma unroll
        for (int h=0;h<8;h++){
            float2 p0=unpack2(acc[n][h][0]), p1=unpack2(acc[n][h][1]);
            float mx=fmaxf(fmaxf(p0.x,p0.y),fmaxf(p1.x,p1.y));
            #pragma unroll
            for (int s=16;s>0;s>>=1) mx=fmaxf(mx,__shfl_xor_sync(0xffffffffu,mx,s));
            if (l==0) redA[(n*8+h)*4+w]=mx;
        }
    __syncthreads();
    #pragma unroll
    for (int n=0;n<2;n++)
        #pragma unroll
        for (int h=0;h<8;h++){
            const int c=n*8+h;
            float gm=fmaxf(fmaxf(redA[c*4+0],redA[c*4+1]),
                           fmaxf(redA[c*4+2],redA[c*4+3]));
            float2 p0=unpack2(acc[n][h][0]), p1=unpack2(acc[n][h][1]);
            p0.x=__expf(p0.x-gm); p0.y=__expf(p0.y-gm);
            p1.x=__expf(p1.x-gm); p1.y=__expf(p1.y-gm);
            acc[n][h][0]=pack2(p0.x,p0.y);
            acc[n][h][1]=pack2(p1.x,p1.y);
            float sum=(p0.x+p0.y)+(p1.x+p1.y);
            #pragma unroll
            for (int s=16;s>0;s>>=1) sum+=__shfl_xor_sync(0xffffffffu,sum,s);
            if (l==0) redB[c*4+w]=sum;
        }
    __syncthreads();
    #pragma unroll
    for (int n=0;n<2;n++)
        #pragma unroll
        for (int h=0;h<8;h++){
            const int c=n*8+h;
            float inv=1.f/(redB[c*4+0]+redB[c*4+1]+redB[c*4+2]+redB[c*4+3]);
            float2 p0=unpack2(acc[n][h][0]), p1=unpack2(acc[n][h][1]);
            float4 o=make_float4(p0.x*inv,p0.y*inv,p1.x*inv,p1.y*inv);
            *(float4*)(g_attn+(((size_t)b*H+h)*N+n0+n)*M+4*t)=o;
        }
}

// ---------------------------------------------------------------------------
// K3: mh = attn @ v. 512 blocks (b,h,16-n), 128 threads.
// ---------------------------------------------------------------------------
__global__ __launch_bounds__(128) void k_av() {
    const int x=blockIdx.x;              // 2*8*32 = 512
    const int b=x>>8, h=(x>>5)&7, n0=(x&31)<<4;
    const int t=threadIdx.x, nl=t>>3, og=t&7;
    __shared__ __align__(16) float at[16][132];
    __shared__ __align__(16) float vt[128][32];
    u64 a01=0ull, a23=0ull;
    for (int mt=0;mt<4;mt++){
        const int mb=mt<<7;
        #pragma unroll
        for (int j=0;j<4;j++){int idx=t+128*j,r=idx>>5,c=idx&31;
            *(float4*)&at[r][c*4]=
                *(const float4*)(g_attn+(((size_t)b*H+h)*N+n0+r)*M+mb+c*4);}
        #pragma unroll
        for (int j=0;j<8;j++){int idx=t+128*j,ml=idx>>3,c=idx&7;
            *(float4*)&vt[ml][c*4]=
                *(const float4*)(g_v+(((size_t)b*M+mb+ml)*H+h)*O+c*4);}
        __syncthreads();
        #pragma unroll 8
        for (int m=0;m<128;m++){
            float a=at[nl][m];
            u64 a2=pack2(a,a);
            ulonglong2 V=*(const ulonglong2*)&vt[m][og*4];
            fma2(a01,a2,V.x);
            fma2(a23,a2,V.y);
        }
        __syncthreads();
    }
    float2 x01=unpack2(a01), x23=unpack2(a23);
    float4 outv=make_float4(x01.x,x01.y,x23.x,x23.y);
    *(float4*)&g_mh[((size_t)(b*N+n0+nl)*H+h)*O+og*4]=outv;
}

// ---------------------------------------------------------------------------
// K4 v3: out = mh @ Wp + bias. 256 blocks (4 n), 512 thr = (jj, k-quarter).
// ---------------------------------------------------------------------------
__global__ __launch_bounds__(512) void k_proj(const float* __restrict__ Wp,
                                              const float* __restrict__ bias,
                                              float* __restrict__ out) {
    const int x=blockIdx.x;              // B*N/4 = 256
    const int b=x>>7, n0=(x&127)<<2, t=threadIdx.x;
    const int jj=t&127, kq=t>>7;
    __shared__ float mhs[4][H*O];
    __shared__ float red[3][4][128];

    #pragma unroll
    for (int j=0;j<2;j++){
        int idx=t+512*j, nl=idx>>8, c=idx&255;
        mhs[nl][c]=g_mh[(size_t)(b*N+n0+nl)*(H*O)+c];
    }
    __syncthreads();

    float acc[4]={0.f,0.f,0.f,0.f};
    const float* wp=Wp+(size_t)(kq*64)*OUTD+jj;
    const int kb=kq*64;
    #pragma unroll 8
    for (int k=0;k<64;k++){
        float wv=wp[(size_t)k*OUTD];
        #pragma unroll
        for (int n=0;n<4;n++) acc[n]=fmaf(mhs[n][kb+k],wv,acc[n]);
    }
    if (kq>0){
        #pragma unroll
        for (int n=0;n<4;n++) red[kq-1][n][jj]=acc[n];
    }
    __syncthreads();
    if (kq==0){
        float bv=bias[jj];
        #pragma unroll
        for (int n=0;n<4;n++){
            float r=acc[n]+red[0][n][jj]+red[1][n][jj]+red[2][n][jj]+bv;
            out[(size_t)(b*N+n0+n)*OUTD+jj]=r;
        }
    }
}

extern "C" void kernel_launch(void* const* d_in, const int* in_sizes, int n_in,
                              void* d_out, int out_size) {
    (void)in_sizes; (void)n_in; (void)out_size;
    const float* query=(const float*)d_in[0];
    const float* key  =(const float*)d_in[1];
    const float* value=(const float*)d_in[2];
    const float* edge =(const float*)d_in[3];
    const float* Wq   =(const float*)d_in[4];
    const float* Wk   =(const float*)d_in[5];
    const float* Wv   =(const float*)d_in[6];
    const float* Wp   =(const float*)d_in[7];
    const float* bias =(const float*)d_in[8];
    float* out=(float*)d_out;

    k_pre <<<384,        256>>>(key,query,Wq,Wk,value,Wv);
    k_attn<<<B*(N/2),    128>>>(edge);
    k_av  <<<B*H*(N/16), 128>>>();
    k_proj<<<B*(N/4),    512>>>(Wp,bias,out);
}